// round 16
// baseline (speedup 1.0000x reference)
#include <cuda_runtime.h>
#include <cuda_bf16.h>
#include <math.h>
#include <stdint.h>

#define S   2048
#define DIM 1024
#define H   16
#define HD  64

#define NEG_INF __int_as_float(0xff800000)

// plane stride for attention operand planes
#define PS (H * S * 64)

// ---------------- scratch (__device__ globals: allocation-free) ----------------
__device__ float g_qr[S*DIM];
__device__ float g_kr[S*DIM];
__device__ float g_vr[S*DIM];
__device__ float g_qi[S*DIM];
__device__ float g_ki[S*DIM];
__device__ float g_vi[S*DIM];

__device__ float2 g_ropetab[S*16];
__device__ float2 g_phtab[DIM];

// bf16 split planes (projection GEMMs)
__device__ __nv_bfloat16 g_real_hi[S*DIM],  g_real_lo[S*DIM];
__device__ __nv_bfloat16 g_imag_hi[S*DIM],  g_imag_lo[S*DIM];
__device__ __nv_bfloat16 g_W_hi[6*DIM*DIM], g_W_lo[6*DIM*DIM];
__device__ __nv_bfloat16 g_Wo_hi[2*DIM*DIM], g_Wo_lo[2*DIM*DIM];
__device__ __nv_bfloat16 g_attn_hi[2*S*DIM], g_attn_lo[2*S*DIM];

// attention operand planes: 12 planes of [h][s][64]
__device__ __nv_bfloat16 g_ap[12 * PS];
__device__ __nv_bfloat16 g_vthi[H*128*S], g_vtlo[H*128*S];  // [h][n][t]

__device__ __forceinline__ uint32_t smem_to_u32(const void* smem_ptr) {
    uint32_t addr;
    asm("{ .reg .u64 tmp; cvta.to.shared.u64 tmp, %1; cvt.u32.u64 %0, tmp; }"
        : "=r"(addr) : "l"(smem_ptr));
    return addr;
}
__device__ __forceinline__ void ldm_x4(uint32_t* r, uint32_t addr) {
    asm volatile("ldmatrix.sync.aligned.m8n8.x4.shared.b16 {%0,%1,%2,%3}, [%4];"
        : "=r"(r[0]), "=r"(r[1]), "=r"(r[2]), "=r"(r[3]) : "r"(addr));
}
__device__ __forceinline__ void mma_bf16(float* c, const uint32_t* a,
                                         uint32_t b0, uint32_t b1) {
    asm volatile("mma.sync.aligned.m16n8k16.row.col.f32.bf16.bf16.f32 "
        "{%0,%1,%2,%3}, {%4,%5,%6,%7}, {%8,%9}, {%0,%1,%2,%3};"
        : "+f"(c[0]), "+f"(c[1]), "+f"(c[2]), "+f"(c[3])
        : "r"(a[0]), "r"(a[1]), "r"(a[2]), "r"(a[3]), "r"(b0), "r"(b1));
}
__device__ __forceinline__ void cp16(uint32_t dst, const void* src) {
    asm volatile("cp.async.cg.shared.global [%0], [%1], 16;" :: "r"(dst), "l"(src));
}
__device__ __forceinline__ void cp_commit() {
    asm volatile("cp.async.commit_group;" ::: "memory");
}
template<int N> __device__ __forceinline__ void cp_wait() {
    asm volatile("cp.async.wait_group %0;" :: "n"(N) : "memory");
}

// swizzle within a plane of 128B rows (8 chunks of 16B per row)
__device__ __forceinline__ uint32_t swz(int r, int c) {
    return (uint32_t)(r * 128 + ((c ^ (r & 7)) << 4));
}

__device__ __forceinline__ void split_store(__nv_bfloat16* hi, __nv_bfloat16* lo,
                                            size_t o, float v) {
    __nv_bfloat16 h = __float2bfloat16(v);
    hi[o] = h;
    lo[o] = __float2bfloat16(v - __bfloat162float(h));
}

// ---------------- fp32 -> (hi, lo) bf16 split (batched) + trig tables ----------------
struct SplitArgs {
    const float*   x[12];
    __nv_bfloat16* hi[12];
    __nv_bfloat16* lo[12];
    int            n4[12];
    const float*   freqs;
    const float*   phase;
    float2*        ropetab;
    float2*        phtab;
};

__device__ __forceinline__ void split_body(const float* __restrict__ x,
                                           __nv_bfloat16* __restrict__ hi,
                                           __nv_bfloat16* __restrict__ lo, int i)
{
    float4 v = ((const float4*)x)[i];
    __nv_bfloat16 h0 = __float2bfloat16(v.x);
    __nv_bfloat16 h1 = __float2bfloat16(v.y);
    __nv_bfloat16 h2 = __float2bfloat16(v.z);
    __nv_bfloat16 h3 = __float2bfloat16(v.w);
    __nv_bfloat162 hA; hA.x = h0; hA.y = h1;
    __nv_bfloat162 hB; hB.x = h2; hB.y = h3;
    ((__nv_bfloat162*)hi)[2*i]   = hA;
    ((__nv_bfloat162*)hi)[2*i+1] = hB;
    __nv_bfloat162 lA, lB;
    lA.x = __float2bfloat16(v.x - __bfloat162float(h0));
    lA.y = __float2bfloat16(v.y - __bfloat162float(h1));
    lB.x = __float2bfloat16(v.z - __bfloat162float(h2));
    lB.y = __float2bfloat16(v.w - __bfloat162float(h3));
    ((__nv_bfloat162*)lo)[2*i]   = lA;
    ((__nv_bfloat162*)lo)[2*i+1] = lB;
}

__global__ void split_many_kernel(SplitArgs sa)
{
    int z = blockIdx.y;
    int i = blockIdx.x * 256 + threadIdx.x;
    if (z == 0) {
        if (i < S * 16) {
            int s = i >> 4, j = i & 15;
            float sn, cs;
            sincosf((float)s * sa.freqs[j], &sn, &cs);
            float2 v; v.x = cs; v.y = sn;
            sa.ropetab[i] = v;
        }
        if (i < DIM) {
            float sn, cs;
            sincosf(sa.phase[i], &sn, &cs);
            float2 v; v.x = cs; v.y = sn;
            sa.phtab[i] = v;
        }
    }
    if (i >= sa.n4[z]) return;
    split_body(sa.x[z], sa.hi[z], sa.lo[z], i);
}

// ---------------- batched mma.sync GEMM: C = A·Bᵀ + bias (bf16x3) ----------------
struct MMArgs {
    const __nv_bfloat16* Ahi[8];
    const __nv_bfloat16* Alo[8];
    const __nv_bfloat16* Bhi[8];
    const __nv_bfloat16* Blo[8];
    const float*         bias[8];
    float*               C[8];
};

#define MM_STAGE 65536u

__global__ __launch_bounds__(256, 1)
void mm_bf16x3_kernel(MMArgs ga, int M, int N, int K)
{
    extern __shared__ __align__(1024) char smem[];
    const int z = blockIdx.z;
    const __nv_bfloat16* __restrict__ Ahi = ga.Ahi[z];
    const __nv_bfloat16* __restrict__ Alo = ga.Alo[z];
    const __nv_bfloat16* __restrict__ Bhi = ga.Bhi[z];
    const __nv_bfloat16* __restrict__ Blo = ga.Blo[z];
    const float* __restrict__ bias = ga.bias[z];
    float* __restrict__       C    = ga.C[z];

    const int m0 = blockIdx.y * 128;
    const int n0 = blockIdx.x * 128;

    const int tid  = threadIdx.x;
    const int lane = tid & 31;
    const int wid  = tid >> 5;
    const int wm   = (wid & 1) * 64;
    const int wn   = (wid >> 1) * 32;

    uint32_t sb = smem_to_u32(smem);

    float acc[4][4][4];
#pragma unroll
    for (int a = 0; a < 4; a++)
#pragma unroll
        for (int b = 0; b < 4; b++)
#pragma unroll
            for (int c = 0; c < 4; c++) acc[a][b][c] = 0.f;

    const int NIT = K / 64;

    auto fill = [&](int it, int buf) {
        int k0 = it * 64;
        uint32_t so = sb + buf * MM_STAGE;
#pragma unroll
        for (int i = 0; i < 4; i++) {
            int q = tid + i * 256;
            int r = q >> 3, c = q & 7;
            uint32_t off = swz(r, c);
            cp16(so +          off, Ahi + (size_t)(m0 + r) * K + k0 + c * 8);
            cp16(so + 16384u + off, Alo + (size_t)(m0 + r) * K + k0 + c * 8);
            cp16(so + 32768u + off, Bhi + (size_t)(n0 + r) * K + k0 + c * 8);
            cp16(so + 49152u + off, Blo + (size_t)(n0 + r) * K + k0 + c * 8);
        }
    };

    fill(0, 0);
    cp_commit();

    for (int it = 0; it < NIT; it++) {
        if (it + 1 < NIT) { fill(it + 1, (it + 1) & 1); cp_commit(); cp_wait<1>(); }
        else              { cp_wait<0>(); }
        __syncthreads();

        uint32_t so = sb + (uint32_t)(it & 1) * MM_STAGE;
#pragma unroll
        for (int kk = 0; kk < 64; kk += 16) {
            int ck = kk >> 3;
            uint32_t ah[4][4], al[4][4];
#pragma unroll
            for (int mt = 0; mt < 4; mt++) {
                int r = wm + mt * 16 + (lane & 15);
                int c = ck + (lane >> 4);
                uint32_t off = swz(r, c);
                ldm_x4(ah[mt], so + off);
                ldm_x4(al[mt], so + 16384u + off);
            }
            uint32_t bh[2][4], bl[2][4];
#pragma unroll
            for (int p = 0; p < 2; p++) {
                int r = wn + p * 16 + (lane & 7) + ((lane >> 4) << 3);
                int c = ck + ((lane >> 3) & 1);
                uint32_t off = swz(r, c);
                ldm_x4(bh[p], so + 32768u + off);
                ldm_x4(bl[p], so + 49152u + off);
            }
#pragma unroll
            for (int mt = 0; mt < 4; mt++)
#pragma unroll
                for (int nt = 0; nt < 4; nt++) {
                    uint32_t b0h = bh[nt >> 1][(nt & 1) * 2];
                    uint32_t b1h = bh[nt >> 1][(nt & 1) * 2 + 1];
                    uint32_t b0l = bl[nt >> 1][(nt & 1) * 2];
                    uint32_t b1l = bl[nt >> 1][(nt & 1) * 2 + 1];
                    mma_bf16(acc[mt][nt], ah[mt], b0h, b1h);
                    mma_bf16(acc[mt][nt], ah[mt], b0l, b1l);
                    mma_bf16(acc[mt][nt], al[mt], b0h, b1h);
                }
        }
        __syncthreads();
    }

#pragma unroll
    for (int mt = 0; mt < 4; mt++) {
        int m = m0 + wm + mt * 16 + (lane >> 2);
#pragma unroll
        for (int nt = 0; nt < 4; nt++) {
            int n = n0 + wn + nt * 8 + (lane & 3) * 2;
            float2 bv = *(const float2*)(bias + n);
            float2 o0, o1;
            o0.x = acc[mt][nt][0] + bv.x;
            o0.y = acc[mt][nt][1] + bv.y;
            o1.x = acc[mt][nt][2] + bv.x;
            o1.y = acc[mt][nt][3] + bv.y;
            *(float2*)(C + (size_t)m * N + n)       = o0;
            *(float2*)(C + (size_t)(m + 8) * N + n) = o1;
        }
    }
}

// ---------------- prep: pack_vt + entangle in ONE launch ----------------
__global__ __launch_bounds__(256)
void prep_kernel(const float* __restrict__ qr, const float* __restrict__ qi,
                 const float* __restrict__ kr, const float* __restrict__ ki,
                 const float* __restrict__ vr, const float* __restrict__ vi,
                 const float* __restrict__ ent,
                 const float2* __restrict__ ropetab,
                 const float2* __restrict__ phtab,
                 __nv_bfloat16* __restrict__ ap,
                 __nv_bfloat16* __restrict__ Vthi,
                 __nv_bfloat16* __restrict__ Vtlo)
{
    __shared__ float sm[2 * 64 * 65];
    int tid = threadIdx.x;

    if (blockIdx.x < S) {
        int s = blockIdx.x;
        float* sqr = sm;
        float* sqi = sm + 1024;
        float* skr = sm + 2048;
        float* ski = sm + 3072;
        float* sent = sm + 4096;
        if (tid < H * H) sent[tid] = ent[tid];
        for (int i = tid; i < DIM; i += 256) {
            size_t o = (size_t)s * DIM + i;
            sqr[i] = qr[o]; sqi[i] = qi[o]; skr[i] = kr[o]; ski[i] = ki[o];
        }
        __syncthreads();

        {
            int h2 = tid >> 4, j = tid & 15;
            float2 cs = ropetab[s * 16 + j];
            int o = h2 * HD + 2 * j;
            float a, b;
            a = sqr[o]; b = sqr[o + 1];
            sqr[o] = a * cs.x - b * cs.y; sqr[o + 1] = a * cs.y + b * cs.x;
            a = skr[o]; b = skr[o + 1];
            skr[o] = a * cs.x - b * cs.y; skr[o + 1] = a * cs.y + b * cs.x;
            a = sqi[o]; b = sqi[o + 1];
            sqi[o] = a * cs.x - b * cs.y; sqi[o + 1] = a * cs.y + b * cs.x;
            a = ski[o]; b = ski[o + 1];
            ski[o] = a * cs.x - b * cs.y; ski[o + 1] = a * cs.y + b * cs.x;
        }
        __syncthreads();

        for (int p = tid; p < DIM; p += 256) {
            int x = p >> 6, d = p & 63;
            float aqr = 0.f, aqi = 0.f, akr = 0.f, aki = 0.f;
#pragma unroll
            for (int h2 = 0; h2 < H; h2++) {
                float e = sent[h2 * H + x];
                int o = h2 * HD + d;
                aqr = fmaf(sqr[o], e, aqr);
                aqi = fmaf(sqi[o], e, aqi);
                akr = fmaf(skr[o], e, akr);
                aki = fmaf(ski[o], e, aki);
            }
            float2 pcps = phtab[p];
            float pc = pcps.x, ps = pcps.y;
            float qr2 = aqr * pc - aqi * ps;
            float qi2 = aqr * ps + aqi * pc;
            float kr2 = akr * pc - aki * ps;
            float ki2 = akr * ps + aki * pc;
            size_t idx = ((size_t)x * S + s) * 64 + d;
            split_store(ap + 0 * PS, ap + 1 * PS, idx, qr2);
            split_store(ap + 2 * PS, ap + 3 * PS, idx, qi2);
            split_store(ap + 4 * PS, ap + 5 * PS, idx, qr2 + qi2);
            split_store(ap + 6 * PS, ap + 7 * PS, idx, kr2);
            split_store(ap + 8 * PS, ap + 9 * PS, idx, ki2);
            split_store(ap + 10 * PS, ap + 11 * PS, idx, kr2 + ki2);
        }
    } else {
        int lin = blockIdx.x - S;
        int h  = lin >> 5;
        int t0 = (lin & 31) * 64;
        float (*tr)[65]  = (float (*)[65])sm;
        float (*tim)[65] = (float (*)[65])(sm + 64 * 65);
#pragma unroll
        for (int i = 0; i < 16; i++) {
            int q = tid + i * 256;
            int t = q >> 6, c = q & 63;
            tr[t][c]  = vr[(size_t)(t0 + t) * DIM + h * HD + c];
            tim[t][c] = vi[(size_t)(t0 + t) * DIM + h * HD + c];
        }
        __syncthreads();
#pragma unroll
        for (int i = 0; i < 32; i++) {
            int q = tid + i * 256;
            int c = q >> 6, t = q & 63;
            float v = (c < 64) ? tr[t][c] : tim[t][c - 64];
            size_t o = ((size_t)(h * 128 + c)) * S + t0 + t;
            split_store(Vthi, Vtlo, o, v);
        }
    }
}

// ---------------- fused flash attention: ADJACENT paired tiles ----------
// CTA bx handles Q-tiles tiA = 30-2*bx (warps 0-3) and tiB = 31-2*bx (warps 4-7).
// bx=0 -> pair (30,31) = longest, launches first.
// smem layout:
//   Q tile A planes 0..5:  sb + pl*8K          (48K)
//   Q tile B planes 0..5:  sb + 49152 + pl*8K  (48K)
//   K stage buf (double):  sb + 98304 + buf*49152, planes 0..5 at +pl*8K (48K each)
//   V (single buffer):     sb + 196608, hi +0 (16K), lo +16K  => total 229376
__global__ __launch_bounds__(256, 1)
void fused_attn_kernel(const __nv_bfloat16* __restrict__ ap,
                       const __nv_bfloat16* __restrict__ Vthi, const __nv_bfloat16* __restrict__ Vtlo,
                       const float* __restrict__ sc_is, const float* __restrict__ sc_at,
                       const float* __restrict__ sc_ce,
                       __nv_bfloat16* __restrict__ Ahi, __nv_bfloat16* __restrict__ Alo)
{
    extern __shared__ __align__(1024) char smem[];
    const int h   = blockIdx.y;
    const int bx  = blockIdx.x;            // 0..15
    const int tiA = 30 - 2 * bx;
    const int tiB = 31 - 2 * bx;
    uint32_t sb = smem_to_u32(smem);
    const int tid = threadIdx.x, lane = tid & 31, wid = tid >> 5;
    const bool grpB = (wid >= 4);
    const int myti = grpB ? tiB : tiA;
    const int m0   = myti * 64;
    const int wm   = (wid & 3) * 16;
    const uint32_t sbQ = sb + (grpB ? 49152u : 0u);

    // Q fill (once)
#pragma unroll
    for (int t = 0; t < 2; t++) {
        int tiq = t ? tiB : tiA;
        uint32_t qb = sb + (uint32_t)t * 49152u;
#pragma unroll
        for (int pl = 0; pl < 6; pl++) {
            const __nv_bfloat16* sp = ap + (size_t)pl * PS + ((size_t)h * S + tiq * 64) * 64;
            uint32_t pb = qb + pl * 8192u;
#pragma unroll
            for (int i = 0; i < 2; i++) {
                int q = tid + i * 256;
                int r = q >> 3, c = q & 7;
                cp16(pb + swz(r, c), sp + (size_t)r * 64 + c * 8);
            }
        }
    }

    auto fillK = [&](int it, int buf) {
        int t0 = it * 64;
        uint32_t so = sb + 98304u + (uint32_t)buf * 49152u;
#pragma unroll
        for (int pl = 0; pl < 6; pl++) {
            const __nv_bfloat16* sp = ap + (size_t)(6 + pl) * PS + ((size_t)h * S + t0) * 64;
            uint32_t pb = so + pl * 8192u;
#pragma unroll
            for (int i = 0; i < 2; i++) {
                int q = tid + i * 256;
                int r = q >> 3, c = q & 7;
                cp16(pb + swz(r, c), sp + (size_t)r * 64 + c * 8);
            }
        }
    };
    auto fillV = [&](int it) {
        int t0 = it * 64;
        uint32_t vb = sb + 196608u;
#pragma unroll
        for (int pl = 0; pl < 2; pl++) {
            const __nv_bfloat16* sp = (pl ? Vtlo : Vthi) + (size_t)(h * 128) * S + t0;
            uint32_t pb = vb + pl * 16384u;
#pragma unroll
            for (int i = 0; i < 4; i++) {
                int q = tid + i * 256;
                int r = q >> 3, c = q & 7;
                cp16(pb + swz(r, c), sp + (size_t)r * S + c * 8);
            }
        }
    };

    fillK(0, 0);
    fillV(0);
    cp_commit();

    float strength = 1.0f / (1.0f + expf(-*sc_is));
    float temp     = fmaxf(expf(*sc_at), 0.1f);
    float eps      = 0.03f / (1.0f + expf(-*sc_ce));
    float factor   = strength / temp;

    float outacc[16][4];
#pragma unroll
    for (int aa = 0; aa < 16; aa++)
#pragma unroll
        for (int c = 0; c < 4; c++) outacc[aa][c] = 0.f;
    float M2[2] = {NEG_INF, NEG_INF};
    float L2[2] = {0.f, 0.f};

    const int rowA = m0 + wm + (lane >> 2);
    const int rowB = rowA + 8;
    const int nit  = tiB + 1;

    cp_wait<0>();
    __syncthreads();

    for (int it = 0; it < nit; it++) {
        uint32_t so = sb + 98304u + (uint32_t)(it & 1) * 49152u;
        int t0 = it * 64;
        const bool active = grpB || (it <= tiA);

        // prefetch next K stage early (hidden behind scores)
        if (it + 1 < nit) { fillK(it + 1, (it + 1) & 1); cp_commit(); }

        float mag[8][4];
        if (active) {
            // ---- Karatsuba scores, two 32-col halves ----
#pragma unroll
            for (int half = 0; half < 2; half++) {
                float k1[4][4], k2[4][4], k3[4][4];
#pragma unroll
                for (int aa = 0; aa < 4; aa++)
#pragma unroll
                    for (int c = 0; c < 4; c++) { k1[aa][c] = 0.f; k2[aa][c] = 0.f; k3[aa][c] = 0.f; }

#pragma unroll
                for (int ckp = 0; ckp < 8; ckp += 2) {
                    uint32_t aQR_h[4], aQR_l[4], aQI_h[4], aQI_l[4], aQS_h[4], aQS_l[4];
                    {
                        int r = wm + (lane & 15);
                        int cg = ckp + (lane >> 4);
                        uint32_t off = swz(r, cg);
                        ldm_x4(aQR_h, sbQ +      0u + off);
                        ldm_x4(aQR_l, sbQ +  8192u + off);
                        ldm_x4(aQI_h, sbQ + 16384u + off);
                        ldm_x4(aQI_l, sbQ + 24576u + off);
                        ldm_x4(aQS_h, sbQ + 32768u + off);
                        ldm_x4(aQS_l, sbQ + 40960u + off);
                    }
#pragma unroll
                    for (int pp = 0; pp < 2; pp++) {
                        int p = half * 2 + pp;
                        int r = p * 16 + (lane & 7) + ((lane >> 4) << 3);
                        int cg = ckp + ((lane >> 3) & 1);
                        uint32_t off = swz(r, cg);
                        uint32_t bKR_h[4], bKR_l[4], bKI_h[4], bKI_l[4], bKS_h[4], bKS_l[4];
                        ldm_x4(bKR_h, so +      0u + off);
                        ldm_x4(bKR_l, so +  8192u + off);
                        ldm_x4(bKI_h, so + 16384u + off);
                        ldm_x4(bKI_l, so + 24576u + off);
                        ldm_x4(bKS_h, so + 32768u + off);
                        ldm_x4(bKS_l, so + 40960u + off);
#pragma unroll
                        for (int e2 = 0; e2 < 2; e2++) {
                            int lnt = pp * 2 + e2, e = e2 * 2;
                            mma_bf16(k1[lnt], aQR_h, bKR_h[e], bKR_h[e + 1]);
                            mma_bf16(k2[lnt], aQI_h, bKI_h[e], bKI_h[e + 1]);
                            mma_bf16(k3[lnt], aQS_h, bKS_h[e], bKS_h[e + 1]);
                        }
#pragma unroll
                        for (int e2 = 0; e2 < 2; e2++) {
                            int lnt = pp * 2 + e2, e = e2 * 2;
                            mma_bf16(k1[lnt], aQR_h, bKR_l[e], bKR_l[e + 1]);
                            mma_bf16(k2[lnt], aQI_h, bKI_l[e], bKI_l[e + 1]);
                            mma_bf16(k3[lnt], aQS_h, bKS_l[e], bKS_l[e + 1]);
                        }
#pragma unroll
                        for (int e2 = 0; e2 < 2; e2++) {
                            int lnt = pp * 2 + e2, e = e2 * 2;
                            mma_bf16(k1[lnt], aQR_l, bKR_h[e], bKR_h[e + 1]);
                            mma_bf16(k2[lnt], aQI_l, bKI_h[e], bKI_h[e + 1]);
                            mma_bf16(k3[lnt], aQS_l, bKS_h[e], bKS_h[e + 1]);
                        }
                    }
                }

#pragma unroll
                for (int lnt = 0; lnt < 4; lnt++) {
                    int nt = half * 4 + lnt;
                    int cbase = t0 + nt * 8 + (lane & 3) * 2;
#pragma unroll
                    for (int j = 0; j < 4; j++) {
                        float r  = (k1[lnt][j] - k2[lnt][j]) * 0.125f;
                        float im = (k3[lnt][j] - k1[lnt][j] - k2[lnt][j]) * 0.125f;
                        float ar = r + eps * im;
                        float ai = im - eps * r;
                        float m  = sqrtf(ar * ar + ai * ai + 1e-6f) * factor;
                        int col = cbase + (j & 1);
                        int row = (j < 2) ? rowA : rowB;
                        mag[nt][j] = (col <= row) ? m : NEG_INF;
                    }
                }
            }
        }

        // V[it] visibility: drain everything except the newest group (K[it+1])
        if (it + 1 < nit) cp_wait<1>(); else cp_wait<0>();
        __syncthreads();

        if (active) {
            // ---- online softmax ----
            float mxA = NEG_INF, mxB = NEG_INF;
#pragma unroll
            for (int nt = 0; nt < 8; nt++) {
                mxA = fmaxf(mxA, fmaxf(mag[nt][0], mag[nt][1]));
                mxB = fmaxf(mxB, fmaxf(mag[nt][2], mag[nt][3]));
            }
            mxA = fmaxf(mxA, __shfl_xor_sync(0xffffffffu, mxA, 1));
            mxA = fmaxf(mxA, __shfl_xor_sync(0xffffffffu, mxA, 2));
            mxB = fmaxf(mxB, __shfl_xor_sync(0xffffffffu, mxB, 1));
            mxB = fmaxf(mxB, __shfl_xor_sync(0xffffffffu, mxB, 2));
            float MnA = fmaxf(M2[0], mxA), MnB = fmaxf(M2[1], mxB);
            float scA = __expf(M2[0] - MnA), scB = __expf(M2[1] - MnB);
            M2[0] = MnA; M2[1] = MnB;

            float sA = 0.f, sB = 0.f;
            uint32_t pfh[4][4], pfl[4][4];
#pragma unroll
            for (int nt = 0; nt < 8; nt++) {
                float p0 = __expf(mag[nt][0] - MnA);
                float p1 = __expf(mag[nt][1] - MnA);
                float p2 = __expf(mag[nt][2] - MnB);
                float p3 = __expf(mag[nt][3] - MnB);
                sA += p0 + p1; sB += p2 + p3;
                __nv_bfloat162 h01, l01, h23, l23;
                h01.x = __float2bfloat16(p0); h01.y = __float2bfloat16(p1);
                l01.x = __float2bfloat16(p0 - __bfloat162float(h01.x));
                l01.y = __float2bfloat16(p1 - __bfloat162float(h01.y));
                h23.x = __float2bfloat16(p2); h23.y = __float2bfloat16(p3);
                l23.x = __float2bfloat16(p2 - __bfloat162float(h23.x));
                l23.y = __float2bfloat16(p3 - __bfloat162float(h23.y));
                int kk = nt >> 1, sel = (nt & 1) * 2;
                pfh[kk][sel]     = *(uint32_t*)&h01;
                pfh[kk][sel + 1] = *(uint32_t*)&h23;
                pfl[kk][sel]     = *(uint32_t*)&l01;
                pfl[kk][sel + 1] = *(uint32_t*)&l23;
            }
            sA += __shfl_xor_sync(0xffffffffu, sA, 1);
            sA += __shfl_xor_sync(0xffffffffu, sA, 2);
            sB += __shfl_xor_sync(0xffffffffu, sB, 1);
            sB += __shfl_xor_sync(0xffffffffu, sB, 2);
            L2[0] = L2[0] * scA + sA;
            L2[1] = L2[1] * scB + sB;

#pragma unroll
            for (int nt2 = 0; nt2 < 16; nt2++) {
                outacc[nt2][0] *= scA; outacc[nt2][1] *= scA;
                outacc[nt2][2] *= scB; outacc[nt2][3] *= scB;
            }

            // ---- P · V ----
            uint32_t vbase = sb + 196608u;
#pragma unroll
            for (int kk = 0; kk < 4; kk++) {
#pragma unroll
                for (int p2 = 0; p2 < 8; p2++) {
                    int r = p2 * 16 + (lane & 7) + ((lane >> 4) << 3);
                    int cg = kk * 2 + ((lane >> 3) & 1);
                    uint32_t off = swz(r, cg);
                    uint32_t vh[4], vl[4];
                    ldm_x4(vh, vbase + off);
                    ldm_x4(vl, vbase + 16384u + off);
#pragma unroll
                    for (int e2 = 0; e2 < 2; e2++) {
                        int nt2 = p2 * 2 + e2, e = e2 * 2;
                        mma_bf16(outacc[nt2], pfh[kk], vh[e], vh[e + 1]);
                    }
#pragma unroll
                    for (int e2 = 0; e2 < 2; e2++) {
                        int nt2 = p2 * 2 + e2, e = e2 * 2;
                        mma_bf16(outacc[nt2], pfh[kk], vl[e], vl[e + 1]);
                    }
#pragma unroll
                    for (int e2 = 0; e2 < 2; e2++) {
                        int nt2 = p2 * 2 + e2, e = e2 * 2;
                        mma_bf16(outacc[nt2], pfl[kk], vh[e], vh[e + 1]);
                    }
                }
            }
        }
        __syncthreads();   // all warps done reading V[it]
        if (it + 1 < nit) {
            fillV(it + 1);
            cp_commit();
            cp_wait<1>();            // drain K[it+1]; V[it+1] still in flight
            __syncthreads();
        }
    }

    // ---- epilogue (per-warp tile) ----
    float invA = 1.0f / L2[0], invB = 1.0f / L2[1];
#pragma unroll
    for (int nt2 = 0; nt2 < 16; nt2++) {
        int col = nt2 * 8 + (lane & 3) * 2;
        size_t pofs = (col < HD) ? 0 : (size_t)S * DIM;
        int d0 = col & 63;
        size_t bA = pofs + (size_t)rowA * DIM + h * HD + d0;
        size_t bB = pofs + (size_t)rowB * DIM + h * HD + d0;
        split_store(Ahi, Alo, bA,     outacc[nt2][0] * invA);
        split_store(Ahi, Alo, bA + 1, outacc[nt2][1] * invA);
        split_store(Ahi, Alo, bB,     outacc[nt2][2] * invB);
        split_store(Ahi, Alo, bB + 1, outacc[nt2][3] * invB);
    }
}

// ---------------- host ----------------
extern "C" void kernel_launch(void* const* d_in, const int* in_sizes, int n_in,
                              void* d_out, int out_size)
{
    const float* real  = (const float*)d_in[0];
    const float* imag  = (const float*)d_in[1];
    const float* Wq_r  = (const float*)d_in[2];
    const float* bq_r  = (const float*)d_in[3];
    const float* Wk_r  = (const float*)d_in[4];
    const float* bk_r  = (const float*)d_in[5];
    const float* Wv_r  = (const float*)d_in[6];
    const float* bv_r  = (const float*)d_in[7];
    const float* Wq_i  = (const float*)d_in[8];
    const float* bq_i  = (const float*)d_in[9];
    const float* Wk_i  = (const float*)d_in[10];
    const float* bk_i  = (const float*)d_in[11];
    const float* Wv_i  = (const float*)d_in[12];
    const float* bv_i  = (const float*)d_in[13];
    const float* Wo_r  = (const float*)d_in[14];
    const float* bo_r  = (const float*)d_in[15];
    const float* Wo_i  = (const float*)d_in[16];
    const float* bo_i  = (const float*)d_in[17];
    const float* phase = (const float*)d_in[18];
    const float* ent   = (const float*)d_in[19];
    const float* rfreq = (const float*)d_in[20];
    const float* s_is  = (const float*)d_in[21];
    const float* s_at  = (const float*)d_in[22];
    const float* s_ce  = (const float*)d_in[23];

    float *qr, *kr, *vr, *qi, *ki, *vi;
    cudaGetSymbolAddress((void**)&qr, g_qr);
    cudaGetSymbolAddress((void**)&kr, g_kr);
    cudaGetSymbolAddress((void**)&vr, g_vr);
    cudaGetSymbolAddress((void**)&qi, g_qi);
    cudaGetSymbolAddress((void**)&ki, g_ki);
    cudaGetSymbolAddress((void**)&vi, g_vi);

    float2 *ropetab, *phtab;
    cudaGetSymbolAddress((void**)&ropetab, g_ropetab);
    cudaGetSymbolAddress((void**)&phtab,   g_phtab);

    __nv_bfloat16 *rhi, *rlo, *ihi, *ilo, *whi, *wlo, *wohi, *wolo, *ahi, *alo;
    cudaGetSymbolAddress((void**)&rhi,  g_real_hi);
    cudaGetSymbolAddress((void**)&rlo,  g_real_lo);
    cudaGetSymbolAddress((void**)&ihi,  g_imag_hi);
    cudaGetSymbolAddress((void**)&ilo,  g_imag_lo);
    cudaGetSymbolAddress((void**)&whi,  g_W_hi);
    cudaGetSymbolAddress((void**)&wlo,  g_W_lo);
    cudaGetSymbolAddress((void**)&wohi, g_Wo_hi);
    cudaGetSymbolAddress((void**)&wolo, g_Wo_lo);
    cudaGetSymbolAddress((void**)&ahi,  g_attn_hi);
    cudaGetSymbolAddress((void**)&alo,  g_attn_lo);

    __nv_bfloat16 *ap, *vthi, *vtlo;
    cudaGetSymbolAddress((void**)&ap,   g_ap);
    cudaGetSymbolAddress((void**)&vthi, g_vthi);
    cudaGetSymbolAddress((void**)&vtlo, g_vtlo);

    float* out = (float*)d_out;

    cudaFuncSetAttribute(mm_bf16x3_kernel,
                         cudaFuncAttributeMaxDynamicSharedMemorySize, 2 * MM_STAGE);
    cudaFuncSetAttribute(fused_attn_kernel,
                         cudaFuncAttributeMaxDynamicSharedMemorySize, 229376);

    const int SD4 = S * DIM / 4;
    const int DD4 = DIM * DIM / 4;

    // 1) splits + trig tables (one batched launch)
    SplitArgs sa = {};
    sa.x[0] = real; sa.hi[0] = rhi; sa.lo[0] = rlo; sa.n4[0] = SD4;
    sa.x[1] = imag; sa.hi[1] = ihi; sa.lo[1] = ilo; sa.n4[1] = SD4;
    const float* Ws[6] = {Wq_r, Wk_r, Wv_r, Wq_i, Wk_i, Wv_i};
    for (int w = 0; w < 6; w++) {
        sa.x[2 + w]  = Ws[w];
        sa.hi[2 + w] = whi + (size_t)w * DIM * DIM;
        sa.lo[2 + w] = wlo + (size_t)w * DIM * DIM;
        sa.n4[2 + w] = DD4;
    }
    sa.x[8] = Wo_r; sa.hi[8] = wohi; sa.lo[8] = wolo; sa.n4[8] = DD4;
    sa.x[9] = Wo_i; sa.hi[9] = wohi + (size_t)DIM * DIM;
    sa.lo[9] = wolo + (size_t)DIM * DIM; sa.n4[9] = DD4;
    sa.freqs = rfreq; sa.phase = phase; sa.ropetab = ropetab; sa.phtab = phtab;
    split_many_kernel<<<dim3(SD4 / 256, 10), 256>>>(sa);

    // 2) six input projections (mma.sync bf16x3)
    MMArgs gp = {};
    float* outs6[6]      = {qr, kr, vr, qi, ki, vi};
    const float* bs6[6]  = {bq_r, bk_r, bv_r, bq_i, bk_i, bv_i};
    for (int w = 0; w < 6; w++) {
        gp.Ahi[w] = (w < 3) ? rhi : ihi;
        gp.Alo[w] = (w < 3) ? rlo : ilo;
        gp.Bhi[w] = whi + (size_t)w * DIM * DIM;
        gp.Blo[w] = wlo + (size_t)w * DIM * DIM;
        gp.bias[w] = bs6[w];
        gp.C[w]   = outs6[w];
    }
    mm_bf16x3_kernel<<<dim3(DIM / 128, S / 128, 6), 256, 2 * MM_STAGE>>>(gp, S, DIM, DIM);

    // 3) prep: entanglement + RoPE + phase planes AND V transpose (one launch)
    prep_kernel<<<S + 512, 256>>>(qr, qi, kr, ki, vr, vi, ent, ropetab, phtab,
                                  ap, vthi, vtlo);

    // 4) fused attention (adjacent paired tiles, pipelined KV)
    fused_attn_kernel<<<dim3(16, H), 256, 229376>>>(ap, vthi, vtlo,
                                                    s_is, s_at, s_ce, ahi, alo);

    // 5) two output projections
    MMArgs go = {};
    go.Ahi[0] = ahi;              go.Alo[0] = alo;
    go.Bhi[0] = wohi;             go.Blo[0] = wolo;
    go.bias[0] = bo_r;            go.C[0] = out;
    go.Ahi[1] = ahi + (size_t)S * DIM;  go.Alo[1] = alo + (size_t)S * DIM;
    go.Bhi[1] = wohi + (size_t)DIM * DIM; go.Blo[1] = wolo + (size_t)DIM * DIM;
    go.bias[1] = bo_i;            go.C[1] = out + (size_t)S * DIM;
    mm_bf16x3_kernel<<<dim3(DIM / 128, S / 128, 2), 256, 2 * MM_STAGE>>>(go, S, DIM, DIM);
}

// round 17
// speedup vs baseline: 1.2307x; 1.2307x over previous
#include <cuda_runtime.h>
#include <cuda_bf16.h>
#include <math.h>
#include <stdint.h>

#define S   2048
#define DIM 1024
#define H   16
#define HD  64

#define NEG_INF __int_as_float(0xff800000)

// plane stride for attention operand planes
#define PS (H * S * 64)

// ---------------- scratch (__device__ globals: allocation-free) ----------------
__device__ float g_qr[S*DIM];
__device__ float g_kr[S*DIM];
__device__ float g_vr[S*DIM];
__device__ float g_qi[S*DIM];
__device__ float g_ki[S*DIM];
__device__ float g_vi[S*DIM];

__device__ float2 g_ropetab[S*16];
__device__ float2 g_phtab[DIM];

// bf16 split planes (projection GEMMs)
__device__ __nv_bfloat16 g_real_hi[S*DIM],  g_real_lo[S*DIM];
__device__ __nv_bfloat16 g_imag_hi[S*DIM],  g_imag_lo[S*DIM];
__device__ __nv_bfloat16 g_W_hi[6*DIM*DIM], g_W_lo[6*DIM*DIM];
__device__ __nv_bfloat16 g_Wo_hi[2*DIM*DIM], g_Wo_lo[2*DIM*DIM];
__device__ __nv_bfloat16 g_attn_hi[2*S*DIM], g_attn_lo[2*S*DIM];

// attention operand planes: 12 planes of [h][s][64]
__device__ __nv_bfloat16 g_ap[12 * PS];
__device__ __nv_bfloat16 g_vthi[H*128*S], g_vtlo[H*128*S];  // [h][n][t]

__device__ __forceinline__ uint32_t smem_to_u32(const void* smem_ptr) {
    uint32_t addr;
    asm("{ .reg .u64 tmp; cvta.to.shared.u64 tmp, %1; cvt.u32.u64 %0, tmp; }"
        : "=r"(addr) : "l"(smem_ptr));
    return addr;
}
__device__ __forceinline__ void ldm_x4(uint32_t* r, uint32_t addr) {
    asm volatile("ldmatrix.sync.aligned.m8n8.x4.shared.b16 {%0,%1,%2,%3}, [%4];"
        : "=r"(r[0]), "=r"(r[1]), "=r"(r[2]), "=r"(r[3]) : "r"(addr));
}
__device__ __forceinline__ void mma_bf16(float* c, const uint32_t* a,
                                         uint32_t b0, uint32_t b1) {
    asm volatile("mma.sync.aligned.m16n8k16.row.col.f32.bf16.bf16.f32 "
        "{%0,%1,%2,%3}, {%4,%5,%6,%7}, {%8,%9}, {%0,%1,%2,%3};"
        : "+f"(c[0]), "+f"(c[1]), "+f"(c[2]), "+f"(c[3])
        : "r"(a[0]), "r"(a[1]), "r"(a[2]), "r"(a[3]), "r"(b0), "r"(b1));
}
__device__ __forceinline__ void cp16(uint32_t dst, const void* src) {
    asm volatile("cp.async.cg.shared.global [%0], [%1], 16;" :: "r"(dst), "l"(src));
}
__device__ __forceinline__ void cp_commit() {
    asm volatile("cp.async.commit_group;" ::: "memory");
}
template<int N> __device__ __forceinline__ void cp_wait() {
    asm volatile("cp.async.wait_group %0;" :: "n"(N) : "memory");
}

// swizzle within a plane of 128B rows (8 chunks of 16B per row)
__device__ __forceinline__ uint32_t swz(int r, int c) {
    return (uint32_t)(r * 128 + ((c ^ (r & 7)) << 4));
}

__device__ __forceinline__ void split_store(__nv_bfloat16* hi, __nv_bfloat16* lo,
                                            size_t o, float v) {
    __nv_bfloat16 h = __float2bfloat16(v);
    hi[o] = h;
    lo[o] = __float2bfloat16(v - __bfloat162float(h));
}

// ---------------- fp32 -> (hi, lo) bf16 split (batched) + trig tables ----------------
struct SplitArgs {
    const float*   x[12];
    __nv_bfloat16* hi[12];
    __nv_bfloat16* lo[12];
    int            n4[12];
    const float*   freqs;
    const float*   phase;
    float2*        ropetab;
    float2*        phtab;
};

__device__ __forceinline__ void split_body(const float* __restrict__ x,
                                           __nv_bfloat16* __restrict__ hi,
                                           __nv_bfloat16* __restrict__ lo, int i)
{
    float4 v = ((const float4*)x)[i];
    __nv_bfloat16 h0 = __float2bfloat16(v.x);
    __nv_bfloat16 h1 = __float2bfloat16(v.y);
    __nv_bfloat16 h2 = __float2bfloat16(v.z);
    __nv_bfloat16 h3 = __float2bfloat16(v.w);
    __nv_bfloat162 hA; hA.x = h0; hA.y = h1;
    __nv_bfloat162 hB; hB.x = h2; hB.y = h3;
    ((__nv_bfloat162*)hi)[2*i]   = hA;
    ((__nv_bfloat162*)hi)[2*i+1] = hB;
    __nv_bfloat162 lA, lB;
    lA.x = __float2bfloat16(v.x - __bfloat162float(h0));
    lA.y = __float2bfloat16(v.y - __bfloat162float(h1));
    lB.x = __float2bfloat16(v.z - __bfloat162float(h2));
    lB.y = __float2bfloat16(v.w - __bfloat162float(h3));
    ((__nv_bfloat162*)lo)[2*i]   = lA;
    ((__nv_bfloat162*)lo)[2*i+1] = lB;
}

__global__ void split_many_kernel(SplitArgs sa)
{
    int z = blockIdx.y;
    int i = blockIdx.x * 256 + threadIdx.x;
    if (z == 0) {
        if (i < S * 16) {
            int s = i >> 4, j = i & 15;
            float sn, cs;
            sincosf((float)s * sa.freqs[j], &sn, &cs);
            float2 v; v.x = cs; v.y = sn;
            sa.ropetab[i] = v;
        }
        if (i < DIM) {
            float sn, cs;
            sincosf(sa.phase[i], &sn, &cs);
            float2 v; v.x = cs; v.y = sn;
            sa.phtab[i] = v;
        }
    }
    if (i >= sa.n4[z]) return;
    split_body(sa.x[z], sa.hi[z], sa.lo[z], i);
}

// ---------------- batched mma.sync GEMM: C = A·Bᵀ + bias (bf16x3) ----------------
struct MMArgs {
    const __nv_bfloat16* Ahi[8];
    const __nv_bfloat16* Alo[8];
    const __nv_bfloat16* Bhi[8];
    const __nv_bfloat16* Blo[8];
    const float*         bias[8];
    float*               C[8];
};

#define MM_STAGE 65536u

__global__ __launch_bounds__(256, 1)
void mm_bf16x3_kernel(MMArgs ga, int M, int N, int K)
{
    extern __shared__ __align__(1024) char smem[];
    const int z = blockIdx.z;
    const __nv_bfloat16* __restrict__ Ahi = ga.Ahi[z];
    const __nv_bfloat16* __restrict__ Alo = ga.Alo[z];
    const __nv_bfloat16* __restrict__ Bhi = ga.Bhi[z];
    const __nv_bfloat16* __restrict__ Blo = ga.Blo[z];
    const float* __restrict__ bias = ga.bias[z];
    float* __restrict__       C    = ga.C[z];

    const int m0 = blockIdx.y * 128;
    const int n0 = blockIdx.x * 128;

    const int tid  = threadIdx.x;
    const int lane = tid & 31;
    const int wid  = tid >> 5;
    const int wm   = (wid & 1) * 64;
    const int wn   = (wid >> 1) * 32;

    uint32_t sb = smem_to_u32(smem);

    float acc[4][4][4];
#pragma unroll
    for (int a = 0; a < 4; a++)
#pragma unroll
        for (int b = 0; b < 4; b++)
#pragma unroll
            for (int c = 0; c < 4; c++) acc[a][b][c] = 0.f;

    const int NIT = K / 64;

    auto fill = [&](int it, int buf) {
        int k0 = it * 64;
        uint32_t so = sb + buf * MM_STAGE;
#pragma unroll
        for (int i = 0; i < 4; i++) {
            int q = tid + i * 256;
            int r = q >> 3, c = q & 7;
            uint32_t off = swz(r, c);
            cp16(so +          off, Ahi + (size_t)(m0 + r) * K + k0 + c * 8);
            cp16(so + 16384u + off, Alo + (size_t)(m0 + r) * K + k0 + c * 8);
            cp16(so + 32768u + off, Bhi + (size_t)(n0 + r) * K + k0 + c * 8);
            cp16(so + 49152u + off, Blo + (size_t)(n0 + r) * K + k0 + c * 8);
        }
    };

    fill(0, 0);
    cp_commit();

    for (int it = 0; it < NIT; it++) {
        if (it + 1 < NIT) { fill(it + 1, (it + 1) & 1); cp_commit(); cp_wait<1>(); }
        else              { cp_wait<0>(); }
        __syncthreads();

        uint32_t so = sb + (uint32_t)(it & 1) * MM_STAGE;
#pragma unroll
        for (int kk = 0; kk < 64; kk += 16) {
            int ck = kk >> 3;
            uint32_t ah[4][4], al[4][4];
#pragma unroll
            for (int mt = 0; mt < 4; mt++) {
                int r = wm + mt * 16 + (lane & 15);
                int c = ck + (lane >> 4);
                uint32_t off = swz(r, c);
                ldm_x4(ah[mt], so + off);
                ldm_x4(al[mt], so + 16384u + off);
            }
            uint32_t bh[2][4], bl[2][4];
#pragma unroll
            for (int p = 0; p < 2; p++) {
                int r = wn + p * 16 + (lane & 7) + ((lane >> 4) << 3);
                int c = ck + ((lane >> 3) & 1);
                uint32_t off = swz(r, c);
                ldm_x4(bh[p], so + 32768u + off);
                ldm_x4(bl[p], so + 49152u + off);
            }
#pragma unroll
            for (int mt = 0; mt < 4; mt++)
#pragma unroll
                for (int nt = 0; nt < 4; nt++) {
                    uint32_t b0h = bh[nt >> 1][(nt & 1) * 2];
                    uint32_t b1h = bh[nt >> 1][(nt & 1) * 2 + 1];
                    uint32_t b0l = bl[nt >> 1][(nt & 1) * 2];
                    uint32_t b1l = bl[nt >> 1][(nt & 1) * 2 + 1];
                    mma_bf16(acc[mt][nt], ah[mt], b0h, b1h);
                    mma_bf16(acc[mt][nt], ah[mt], b0l, b1l);
                    mma_bf16(acc[mt][nt], al[mt], b0h, b1h);
                }
        }
        __syncthreads();
    }

#pragma unroll
    for (int mt = 0; mt < 4; mt++) {
        int m = m0 + wm + mt * 16 + (lane >> 2);
#pragma unroll
        for (int nt = 0; nt < 4; nt++) {
            int n = n0 + wn + nt * 8 + (lane & 3) * 2;
            float2 bv = *(const float2*)(bias + n);
            float2 o0, o1;
            o0.x = acc[mt][nt][0] + bv.x;
            o0.y = acc[mt][nt][1] + bv.y;
            o1.x = acc[mt][nt][2] + bv.x;
            o1.y = acc[mt][nt][3] + bv.y;
            *(float2*)(C + (size_t)m * N + n)       = o0;
            *(float2*)(C + (size_t)(m + 8) * N + n) = o1;
        }
    }
}

// ---------------- prep: pack_vt + entangle in ONE launch ----------------
__global__ __launch_bounds__(256)
void prep_kernel(const float* __restrict__ qr, const float* __restrict__ qi,
                 const float* __restrict__ kr, const float* __restrict__ ki,
                 const float* __restrict__ vr, const float* __restrict__ vi,
                 const float* __restrict__ ent,
                 const float2* __restrict__ ropetab,
                 const float2* __restrict__ phtab,
                 __nv_bfloat16* __restrict__ ap,
                 __nv_bfloat16* __restrict__ Vthi,
                 __nv_bfloat16* __restrict__ Vtlo)
{
    __shared__ float sm[2 * 64 * 65];
    int tid = threadIdx.x;

    if (blockIdx.x < S) {
        int s = blockIdx.x;
        float* sqr = sm;
        float* sqi = sm + 1024;
        float* skr = sm + 2048;
        float* ski = sm + 3072;
        float* sent = sm + 4096;
        if (tid < H * H) sent[tid] = ent[tid];
        for (int i = tid; i < DIM; i += 256) {
            size_t o = (size_t)s * DIM + i;
            sqr[i] = qr[o]; sqi[i] = qi[o]; skr[i] = kr[o]; ski[i] = ki[o];
        }
        __syncthreads();

        {
            int h2 = tid >> 4, j = tid & 15;
            float2 cs = ropetab[s * 16 + j];
            int o = h2 * HD + 2 * j;
            float a, b;
            a = sqr[o]; b = sqr[o + 1];
            sqr[o] = a * cs.x - b * cs.y; sqr[o + 1] = a * cs.y + b * cs.x;
            a = skr[o]; b = skr[o + 1];
            skr[o] = a * cs.x - b * cs.y; skr[o + 1] = a * cs.y + b * cs.x;
            a = sqi[o]; b = sqi[o + 1];
            sqi[o] = a * cs.x - b * cs.y; sqi[o + 1] = a * cs.y + b * cs.x;
            a = ski[o]; b = ski[o + 1];
            ski[o] = a * cs.x - b * cs.y; ski[o + 1] = a * cs.y + b * cs.x;
        }
        __syncthreads();

        for (int p = tid; p < DIM; p += 256) {
            int x = p >> 6, d = p & 63;
            float aqr = 0.f, aqi = 0.f, akr = 0.f, aki = 0.f;
#pragma unroll
            for (int h2 = 0; h2 < H; h2++) {
                float e = sent[h2 * H + x];
                int o = h2 * HD + d;
                aqr = fmaf(sqr[o], e, aqr);
                aqi = fmaf(sqi[o], e, aqi);
                akr = fmaf(skr[o], e, akr);
                aki = fmaf(ski[o], e, aki);
            }
            float2 pcps = phtab[p];
            float pc = pcps.x, ps = pcps.y;
            float qr2 = aqr * pc - aqi * ps;
            float qi2 = aqr * ps + aqi * pc;
            float kr2 = akr * pc - aki * ps;
            float ki2 = akr * ps + aki * pc;
            size_t idx = ((size_t)x * S + s) * 64 + d;
            split_store(ap + 0 * PS, ap + 1 * PS, idx, qr2);
            split_store(ap + 2 * PS, ap + 3 * PS, idx, qi2);
            split_store(ap + 4 * PS, ap + 5 * PS, idx, qr2 + qi2);
            split_store(ap + 6 * PS, ap + 7 * PS, idx, kr2);
            split_store(ap + 8 * PS, ap + 9 * PS, idx, ki2);
            split_store(ap + 10 * PS, ap + 11 * PS, idx, kr2 + ki2);
        }
    } else {
        int lin = blockIdx.x - S;
        int h  = lin >> 5;
        int t0 = (lin & 31) * 64;
        float (*tr)[65]  = (float (*)[65])sm;
        float (*tim)[65] = (float (*)[65])(sm + 64 * 65);
#pragma unroll
        for (int i = 0; i < 16; i++) {
            int q = tid + i * 256;
            int t = q >> 6, c = q & 63;
            tr[t][c]  = vr[(size_t)(t0 + t) * DIM + h * HD + c];
            tim[t][c] = vi[(size_t)(t0 + t) * DIM + h * HD + c];
        }
        __syncthreads();
#pragma unroll
        for (int i = 0; i < 32; i++) {
            int q = tid + i * 256;
            int c = q >> 6, t = q & 63;
            float v = (c < 64) ? tr[t][c] : tim[t][c - 64];
            size_t o = ((size_t)(h * 128 + c)) * S + t0 + t;
            split_store(Vthi, Vtlo, o, v);
        }
    }
}

// ---------------- fused flash attention: adjacent paired tiles, LPT order ----
// gridDim = (H, 16): h = blockIdx.x (FAST index), pair = blockIdx.y (SLOW).
// pair p handles Q-tiles tiA = 30-2p (warps 0-3), tiB = 31-2p (warps 4-7).
// Linear dispatch order => all 32-iter CTAs first, then 30, ... (global LPT).
// smem layout:
//   Q tile A planes 0..5:  sb + pl*8K          (48K)
//   Q tile B planes 0..5:  sb + 49152 + pl*8K  (48K)
//   K stage buf (double):  sb + 98304 + buf*49152, planes 0..5 at +pl*8K (48K each)
//   V (single buffer):     sb + 196608, hi +0 (16K), lo +16K  => total 229376
__global__ __launch_bounds__(256, 1)
void fused_attn_kernel(const __nv_bfloat16* __restrict__ ap,
                       const __nv_bfloat16* __restrict__ Vthi, const __nv_bfloat16* __restrict__ Vtlo,
                       const float* __restrict__ sc_is, const float* __restrict__ sc_at,
                       const float* __restrict__ sc_ce,
                       __nv_bfloat16* __restrict__ Ahi, __nv_bfloat16* __restrict__ Alo)
{
    extern __shared__ __align__(1024) char smem[];
    const int h   = blockIdx.x;            // fast index: all heads of a pair adjacent
    const int px  = blockIdx.y;            // slow index: pair 0 = longest (LPT)
    const int tiA = 30 - 2 * px;
    const int tiB = 31 - 2 * px;
    uint32_t sb = smem_to_u32(smem);
    const int tid = threadIdx.x, lane = tid & 31, wid = tid >> 5;
    const bool grpB = (wid >= 4);
    const int myti = grpB ? tiB : tiA;
    const int m0   = myti * 64;
    const int wm   = (wid & 3) * 16;
    const uint32_t sbQ = sb + (grpB ? 49152u : 0u);

    // Q fill (once)
#pragma unroll
    for (int t = 0; t < 2; t++) {
        int tiq = t ? tiB : tiA;
        uint32_t qb = sb + (uint32_t)t * 49152u;
#pragma unroll
        for (int pl = 0; pl < 6; pl++) {
            const __nv_bfloat16* sp = ap + (size_t)pl * PS + ((size_t)h * S + tiq * 64) * 64;
            uint32_t pb = qb + pl * 8192u;
#pragma unroll
            for (int i = 0; i < 2; i++) {
                int q = tid + i * 256;
                int r = q >> 3, c = q & 7;
                cp16(pb + swz(r, c), sp + (size_t)r * 64 + c * 8);
            }
        }
    }

    auto fillK = [&](int it, int buf) {
        int t0 = it * 64;
        uint32_t so = sb + 98304u + (uint32_t)buf * 49152u;
#pragma unroll
        for (int pl = 0; pl < 6; pl++) {
            const __nv_bfloat16* sp = ap + (size_t)(6 + pl) * PS + ((size_t)h * S + t0) * 64;
            uint32_t pb = so + pl * 8192u;
#pragma unroll
            for (int i = 0; i < 2; i++) {
                int q = tid + i * 256;
                int r = q >> 3, c = q & 7;
                cp16(pb + swz(r, c), sp + (size_t)r * 64 + c * 8);
            }
        }
    };
    auto fillV = [&](int it) {
        int t0 = it * 64;
        uint32_t vb = sb + 196608u;
#pragma unroll
        for (int pl = 0; pl < 2; pl++) {
            const __nv_bfloat16* sp = (pl ? Vtlo : Vthi) + (size_t)(h * 128) * S + t0;
            uint32_t pb = vb + pl * 16384u;
#pragma unroll
            for (int i = 0; i < 4; i++) {
                int q = tid + i * 256;
                int r = q >> 3, c = q & 7;
                cp16(pb + swz(r, c), sp + (size_t)r * S + c * 8);
            }
        }
    };

    fillK(0, 0);
    fillV(0);
    cp_commit();

    float strength = 1.0f / (1.0f + expf(-*sc_is));
    float temp     = fmaxf(expf(*sc_at), 0.1f);
    float eps      = 0.03f / (1.0f + expf(-*sc_ce));
    float factor   = strength / temp;

    float outacc[16][4];
#pragma unroll
    for (int aa = 0; aa < 16; aa++)
#pragma unroll
        for (int c = 0; c < 4; c++) outacc[aa][c] = 0.f;
    float M2[2] = {NEG_INF, NEG_INF};
    float L2[2] = {0.f, 0.f};

    const int rowA = m0 + wm + (lane >> 2);
    const int rowB = rowA + 8;
    const int nit  = tiB + 1;

    cp_wait<0>();
    __syncthreads();

    for (int it = 0; it < nit; it++) {
        uint32_t so = sb + 98304u + (uint32_t)(it & 1) * 49152u;
        int t0 = it * 64;
        const bool active = grpB || (it <= tiA);

        // prefetch next K stage early (hidden behind scores)
        if (it + 1 < nit) { fillK(it + 1, (it + 1) & 1); cp_commit(); }

        float mag[8][4];
        if (active) {
            // ---- Karatsuba scores, two 32-col halves ----
#pragma unroll
            for (int half = 0; half < 2; half++) {
                float k1[4][4], k2[4][4], k3[4][4];
#pragma unroll
                for (int aa = 0; aa < 4; aa++)
#pragma unroll
                    for (int c = 0; c < 4; c++) { k1[aa][c] = 0.f; k2[aa][c] = 0.f; k3[aa][c] = 0.f; }

#pragma unroll
                for (int ckp = 0; ckp < 8; ckp += 2) {
                    uint32_t aQR_h[4], aQR_l[4], aQI_h[4], aQI_l[4], aQS_h[4], aQS_l[4];
                    {
                        int r = wm + (lane & 15);
                        int cg = ckp + (lane >> 4);
                        uint32_t off = swz(r, cg);
                        ldm_x4(aQR_h, sbQ +      0u + off);
                        ldm_x4(aQR_l, sbQ +  8192u + off);
                        ldm_x4(aQI_h, sbQ + 16384u + off);
                        ldm_x4(aQI_l, sbQ + 24576u + off);
                        ldm_x4(aQS_h, sbQ + 32768u + off);
                        ldm_x4(aQS_l, sbQ + 40960u + off);
                    }
#pragma unroll
                    for (int pp = 0; pp < 2; pp++) {
                        int p = half * 2 + pp;
                        int r = p * 16 + (lane & 7) + ((lane >> 4) << 3);
                        int cg = ckp + ((lane >> 3) & 1);
                        uint32_t off = swz(r, cg);
                        uint32_t bKR_h[4], bKR_l[4], bKI_h[4], bKI_l[4], bKS_h[4], bKS_l[4];
                        ldm_x4(bKR_h, so +      0u + off);
                        ldm_x4(bKR_l, so +  8192u + off);
                        ldm_x4(bKI_h, so + 16384u + off);
                        ldm_x4(bKI_l, so + 24576u + off);
                        ldm_x4(bKS_h, so + 32768u + off);
                        ldm_x4(bKS_l, so + 40960u + off);
#pragma unroll
                        for (int e2 = 0; e2 < 2; e2++) {
                            int lnt = pp * 2 + e2, e = e2 * 2;
                            mma_bf16(k1[lnt], aQR_h, bKR_h[e], bKR_h[e + 1]);
                            mma_bf16(k2[lnt], aQI_h, bKI_h[e], bKI_h[e + 1]);
                            mma_bf16(k3[lnt], aQS_h, bKS_h[e], bKS_h[e + 1]);
                        }
#pragma unroll
                        for (int e2 = 0; e2 < 2; e2++) {
                            int lnt = pp * 2 + e2, e = e2 * 2;
                            mma_bf16(k1[lnt], aQR_h, bKR_l[e], bKR_l[e + 1]);
                            mma_bf16(k2[lnt], aQI_h, bKI_l[e], bKI_l[e + 1]);
                            mma_bf16(k3[lnt], aQS_h, bKS_l[e], bKS_l[e + 1]);
                        }
#pragma unroll
                        for (int e2 = 0; e2 < 2; e2++) {
                            int lnt = pp * 2 + e2, e = e2 * 2;
                            mma_bf16(k1[lnt], aQR_l, bKR_h[e], bKR_h[e + 1]);
                            mma_bf16(k2[lnt], aQI_l, bKI_h[e], bKI_h[e + 1]);
                            mma_bf16(k3[lnt], aQS_l, bKS_h[e], bKS_h[e + 1]);
                        }
                    }
                }

#pragma unroll
                for (int lnt = 0; lnt < 4; lnt++) {
                    int nt = half * 4 + lnt;
                    int cbase = t0 + nt * 8 + (lane & 3) * 2;
#pragma unroll
                    for (int j = 0; j < 4; j++) {
                        float r  = (k1[lnt][j] - k2[lnt][j]) * 0.125f;
                        float im = (k3[lnt][j] - k1[lnt][j] - k2[lnt][j]) * 0.125f;
                        float ar = r + eps * im;
                        float ai = im - eps * r;
                        float m  = sqrtf(ar * ar + ai * ai + 1e-6f) * factor;
                        int col = cbase + (j & 1);
                        int row = (j < 2) ? rowA : rowB;
                        mag[nt][j] = (col <= row) ? m : NEG_INF;
                    }
                }
            }
        }

        // V[it] visibility: drain everything except the newest group (K[it+1])
        if (it + 1 < nit) cp_wait<1>(); else cp_wait<0>();
        __syncthreads();

        if (active) {
            // ---- online softmax ----
            float mxA = NEG_INF, mxB = NEG_INF;
#pragma unroll
            for (int nt = 0; nt < 8; nt++) {
                mxA = fmaxf(mxA, fmaxf(mag[nt][0], mag[nt][1]));
                mxB = fmaxf(mxB, fmaxf(mag[nt][2], mag[nt][3]));
            }
            mxA = fmaxf(mxA, __shfl_xor_sync(0xffffffffu, mxA, 1));
            mxA = fmaxf(mxA, __shfl_xor_sync(0xffffffffu, mxA, 2));
            mxB = fmaxf(mxB, __shfl_xor_sync(0xffffffffu, mxB, 1));
            mxB = fmaxf(mxB, __shfl_xor_sync(0xffffffffu, mxB, 2));
            float MnA = fmaxf(M2[0], mxA), MnB = fmaxf(M2[1], mxB);
            float scA = __expf(M2[0] - MnA), scB = __expf(M2[1] - MnB);
            M2[0] = MnA; M2[1] = MnB;

            float sA = 0.f, sB = 0.f;
            uint32_t pfh[4][4], pfl[4][4];
#pragma unroll
            for (int nt = 0; nt < 8; nt++) {
                float p0 = __expf(mag[nt][0] - MnA);
                float p1 = __expf(mag[nt][1] - MnA);
                float p2 = __expf(mag[nt][2] - MnB);
                float p3 = __expf(mag[nt][3] - MnB);
                sA += p0 + p1; sB += p2 + p3;
                __nv_bfloat162 h01, l01, h23, l23;
                h01.x = __float2bfloat16(p0); h01.y = __float2bfloat16(p1);
                l01.x = __float2bfloat16(p0 - __bfloat162float(h01.x));
                l01.y = __float2bfloat16(p1 - __bfloat162float(h01.y));
                h23.x = __float2bfloat16(p2); h23.y = __float2bfloat16(p3);
                l23.x = __float2bfloat16(p2 - __bfloat162float(h23.x));
                l23.y = __float2bfloat16(p3 - __bfloat162float(h23.y));
                int kk = nt >> 1, sel = (nt & 1) * 2;
                pfh[kk][sel]     = *(uint32_t*)&h01;
                pfh[kk][sel + 1] = *(uint32_t*)&h23;
                pfl[kk][sel]     = *(uint32_t*)&l01;
                pfl[kk][sel + 1] = *(uint32_t*)&l23;
            }
            sA += __shfl_xor_sync(0xffffffffu, sA, 1);
            sA += __shfl_xor_sync(0xffffffffu, sA, 2);
            sB += __shfl_xor_sync(0xffffffffu, sB, 1);
            sB += __shfl_xor_sync(0xffffffffu, sB, 2);
            L2[0] = L2[0] * scA + sA;
            L2[1] = L2[1] * scB + sB;

#pragma unroll
            for (int nt2 = 0; nt2 < 16; nt2++) {
                outacc[nt2][0] *= scA; outacc[nt2][1] *= scA;
                outacc[nt2][2] *= scB; outacc[nt2][3] *= scB;
            }

            // ---- P · V ----
            uint32_t vbase = sb + 196608u;
#pragma unroll
            for (int kk = 0; kk < 4; kk++) {
#pragma unroll
                for (int p2 = 0; p2 < 8; p2++) {
                    int r = p2 * 16 + (lane & 7) + ((lane >> 4) << 3);
                    int cg = kk * 2 + ((lane >> 3) & 1);
                    uint32_t off = swz(r, cg);
                    uint32_t vh[4], vl[4];
                    ldm_x4(vh, vbase + off);
                    ldm_x4(vl, vbase + 16384u + off);
#pragma unroll
                    for (int e2 = 0; e2 < 2; e2++) {
                        int nt2 = p2 * 2 + e2, e = e2 * 2;
                        mma_bf16(outacc[nt2], pfh[kk], vh[e], vh[e + 1]);
                    }
#pragma unroll
                    for (int e2 = 0; e2 < 2; e2++) {
                        int nt2 = p2 * 2 + e2, e = e2 * 2;
                        mma_bf16(outacc[nt2], pfh[kk], vl[e], vl[e + 1]);
                    }
#pragma unroll
                    for (int e2 = 0; e2 < 2; e2++) {
                        int nt2 = p2 * 2 + e2, e = e2 * 2;
                        mma_bf16(outacc[nt2], pfl[kk], vh[e], vh[e + 1]);
                    }
                }
            }
        }
        __syncthreads();   // all warps done reading V[it]
        if (it + 1 < nit) {
            fillV(it + 1);
            cp_commit();
            cp_wait<1>();            // drain K[it+1]; V[it+1] still in flight
            __syncthreads();
        }
    }

    // ---- epilogue (per-warp tile) ----
    float invA = 1.0f / L2[0], invB = 1.0f / L2[1];
#pragma unroll
    for (int nt2 = 0; nt2 < 16; nt2++) {
        int col = nt2 * 8 + (lane & 3) * 2;
        size_t pofs = (col < HD) ? 0 : (size_t)S * DIM;
        int d0 = col & 63;
        size_t bA = pofs + (size_t)rowA * DIM + h * HD + d0;
        size_t bB = pofs + (size_t)rowB * DIM + h * HD + d0;
        split_store(Ahi, Alo, bA,     outacc[nt2][0] * invA);
        split_store(Ahi, Alo, bA + 1, outacc[nt2][1] * invA);
        split_store(Ahi, Alo, bB,     outacc[nt2][2] * invB);
        split_store(Ahi, Alo, bB + 1, outacc[nt2][3] * invB);
    }
}

// ---------------- host ----------------
extern "C" void kernel_launch(void* const* d_in, const int* in_sizes, int n_in,
                              void* d_out, int out_size)
{
    const float* real  = (const float*)d_in[0];
    const float* imag  = (const float*)d_in[1];
    const float* Wq_r  = (const float*)d_in[2];
    const float* bq_r  = (const float*)d_in[3];
    const float* Wk_r  = (const float*)d_in[4];
    const float* bk_r  = (const float*)d_in[5];
    const float* Wv_r  = (const float*)d_in[6];
    const float* bv_r  = (const float*)d_in[7];
    const float* Wq_i  = (const float*)d_in[8];
    const float* bq_i  = (const float*)d_in[9];
    const float* Wk_i  = (const float*)d_in[10];
    const float* bk_i  = (const float*)d_in[11];
    const float* Wv_i  = (const float*)d_in[12];
    const float* bv_i  = (const float*)d_in[13];
    const float* Wo_r  = (const float*)d_in[14];
    const float* bo_r  = (const float*)d_in[15];
    const float* Wo_i  = (const float*)d_in[16];
    const float* bo_i  = (const float*)d_in[17];
    const float* phase = (const float*)d_in[18];
    const float* ent   = (const float*)d_in[19];
    const float* rfreq = (const float*)d_in[20];
    const float* s_is  = (const float*)d_in[21];
    const float* s_at  = (const float*)d_in[22];
    const float* s_ce  = (const float*)d_in[23];

    float *qr, *kr, *vr, *qi, *ki, *vi;
    cudaGetSymbolAddress((void**)&qr, g_qr);
    cudaGetSymbolAddress((void**)&kr, g_kr);
    cudaGetSymbolAddress((void**)&vr, g_vr);
    cudaGetSymbolAddress((void**)&qi, g_qi);
    cudaGetSymbolAddress((void**)&ki, g_ki);
    cudaGetSymbolAddress((void**)&vi, g_vi);

    float2 *ropetab, *phtab;
    cudaGetSymbolAddress((void**)&ropetab, g_ropetab);
    cudaGetSymbolAddress((void**)&phtab,   g_phtab);

    __nv_bfloat16 *rhi, *rlo, *ihi, *ilo, *whi, *wlo, *wohi, *wolo, *ahi, *alo;
    cudaGetSymbolAddress((void**)&rhi,  g_real_hi);
    cudaGetSymbolAddress((void**)&rlo,  g_real_lo);
    cudaGetSymbolAddress((void**)&ihi,  g_imag_hi);
    cudaGetSymbolAddress((void**)&ilo,  g_imag_lo);
    cudaGetSymbolAddress((void**)&whi,  g_W_hi);
    cudaGetSymbolAddress((void**)&wlo,  g_W_lo);
    cudaGetSymbolAddress((void**)&wohi, g_Wo_hi);
    cudaGetSymbolAddress((void**)&wolo, g_Wo_lo);
    cudaGetSymbolAddress((void**)&ahi,  g_attn_hi);
    cudaGetSymbolAddress((void**)&alo,  g_attn_lo);

    __nv_bfloat16 *ap, *vthi, *vtlo;
    cudaGetSymbolAddress((void**)&ap,   g_ap);
    cudaGetSymbolAddress((void**)&vthi, g_vthi);
    cudaGetSymbolAddress((void**)&vtlo, g_vtlo);

    float* out = (float*)d_out;

    cudaFuncSetAttribute(mm_bf16x3_kernel,
                         cudaFuncAttributeMaxDynamicSharedMemorySize, 2 * MM_STAGE);
    cudaFuncSetAttribute(fused_attn_kernel,
                         cudaFuncAttributeMaxDynamicSharedMemorySize, 229376);

    const int SD4 = S * DIM / 4;
    const int DD4 = DIM * DIM / 4;

    // 1) splits + trig tables (one batched launch)
    SplitArgs sa = {};
    sa.x[0] = real; sa.hi[0] = rhi; sa.lo[0] = rlo; sa.n4[0] = SD4;
    sa.x[1] = imag; sa.hi[1] = ihi; sa.lo[1] = ilo; sa.n4[1] = SD4;
    const float* Ws[6] = {Wq_r, Wk_r, Wv_r, Wq_i, Wk_i, Wv_i};
    for (int w = 0; w < 6; w++) {
        sa.x[2 + w]  = Ws[w];
        sa.hi[2 + w] = whi + (size_t)w * DIM * DIM;
        sa.lo[2 + w] = wlo + (size_t)w * DIM * DIM;
        sa.n4[2 + w] = DD4;
    }
    sa.x[8] = Wo_r; sa.hi[8] = wohi; sa.lo[8] = wolo; sa.n4[8] = DD4;
    sa.x[9] = Wo_i; sa.hi[9] = wohi + (size_t)DIM * DIM;
    sa.lo[9] = wolo + (size_t)DIM * DIM; sa.n4[9] = DD4;
    sa.freqs = rfreq; sa.phase = phase; sa.ropetab = ropetab; sa.phtab = phtab;
    split_many_kernel<<<dim3(SD4 / 256, 10), 256>>>(sa);

    // 2) six input projections (mma.sync bf16x3)
    MMArgs gp = {};
    float* outs6[6]      = {qr, kr, vr, qi, ki, vi};
    const float* bs6[6]  = {bq_r, bk_r, bv_r, bq_i, bk_i, bv_i};
    for (int w = 0; w < 6; w++) {
        gp.Ahi[w] = (w < 3) ? rhi : ihi;
        gp.Alo[w] = (w < 3) ? rlo : ilo;
        gp.Bhi[w] = whi + (size_t)w * DIM * DIM;
        gp.Blo[w] = wlo + (size_t)w * DIM * DIM;
        gp.bias[w] = bs6[w];
        gp.C[w]   = outs6[w];
    }
    mm_bf16x3_kernel<<<dim3(DIM / 128, S / 128, 6), 256, 2 * MM_STAGE>>>(gp, S, DIM, DIM);

    // 3) prep: entanglement + RoPE + phase planes AND V transpose (one launch)
    prep_kernel<<<S + 512, 256>>>(qr, qi, kr, ki, vr, vi, ent, ropetab, phtab,
                                  ap, vthi, vtlo);

    // 4) fused attention (adjacent pairs, LPT launch order: grid (H, pairs))
    fused_attn_kernel<<<dim3(H, 16), 256, 229376>>>(ap, vthi, vtlo,
                                                    s_is, s_at, s_ce, ahi, alo);

    // 5) two output projections
    MMArgs go = {};
    go.Ahi[0] = ahi;              go.Alo[0] = alo;
    go.Bhi[0] = wohi;             go.Blo[0] = wolo;
    go.bias[0] = bo_r;            go.C[0] = out;
    go.Ahi[1] = ahi + (size_t)S * DIM;  go.Alo[1] = alo + (size_t)S * DIM;
    go.Bhi[1] = wohi + (size_t)DIM * DIM; go.Blo[1] = wolo + (size_t)DIM * DIM;
    go.bias[1] = bo_i;            go.C[1] = out + (size_t)S * DIM;
    mm_bf16x3_kernel<<<dim3(DIM / 128, S / 128, 2), 256, 2 * MM_STAGE>>>(go, S, DIM, DIM);
}